// round 11
// baseline (speedup 1.0000x reference)
#include <cuda_runtime.h>
#include <cuda_fp16.h>
#include <math.h>

#define NN    100000
#define FIN   128
#define HID   16
#define NC    2
#define EMAX  3400000
#define OFF_BLK 1024
#define NB_OFF  ((NN + OFF_BLK - 1) / OFF_BLK)   // 98

// ---------------- scratch (device globals: no allocation allowed) ----------
__device__ int    g_cnt[NN];
__device__ int    g_beg[NN];
__device__ int    g_cursor[NN];
__device__ int    g_total;
__device__ int    g_adj[EMAX];
__device__ float  g_dinv[NN];
__device__ __half g_h1s[NN * HID];   // 32B per node row = 1 L2 sector
__device__ float  g_h2s[NN * NC];

// ---------------- CSR build -------------------------------------------------

__global__ void k_count(const int* __restrict__ dst, int E) {
    int t = blockIdx.x * blockDim.x + threadIdx.x;
    if (t == 0) g_total = 0;                      // consumed only by k_offsets
    int e = t * 4;
    if (e + 3 < E) {
        int4 d = *(const int4*)&dst[e];
        atomicAdd(&g_cnt[d.x], 1);
        atomicAdd(&g_cnt[d.y], 1);
        atomicAdd(&g_cnt[d.z], 1);
        atomicAdd(&g_cnt[d.w], 1);
    } else {
        for (int k = e; k < E; k++) atomicAdd(&g_cnt[dst[k]], 1);
    }
}

// offsets via block scan + single atomic block-base (buckets need only be
// disjoint, not ordered by node id)
__global__ void k_offsets() {
    __shared__ int wsum[32];
    __shared__ int base_sh;
    int tid = threadIdx.x;
    int i = blockIdx.x * OFF_BLK + tid;
    int v = (i < NN) ? g_cnt[i] : 0;
    int lane = tid & 31, wid = tid >> 5;
    int inc = v;
    #pragma unroll
    for (int o = 1; o < 32; o <<= 1) {
        int t = __shfl_up_sync(0xffffffffu, inc, o);
        if (lane >= o) inc += t;
    }
    if (lane == 31) wsum[wid] = inc;
    __syncthreads();
    if (wid == 0) {
        int s = wsum[lane];
        #pragma unroll
        for (int o = 1; o < 32; o <<= 1) {
            int t = __shfl_up_sync(0xffffffffu, s, o);
            if (lane >= o) s += t;
        }
        wsum[lane] = s;
        if (lane == 31) base_sh = atomicAdd(&g_total, s);   // block base
    }
    __syncthreads();
    if (i >= NN) return;
    int wbase = (wid > 0) ? wsum[wid - 1] : 0;
    int beg = base_sh + wbase + inc - v;
    g_beg[i] = beg;
    g_cursor[i] = beg;
    g_dinv[i] = rsqrtf((float)v + 1.0f);          // +1 self loop
}

__global__ void k_scatter(const int* __restrict__ src, const int* __restrict__ dst, int E) {
    int t = blockIdx.x * blockDim.x + threadIdx.x;
    int e = t * 4;
    if (e + 3 < E) {
        int4 s = *(const int4*)&src[e];
        int4 d = *(const int4*)&dst[e];
        int p0 = atomicAdd(&g_cursor[d.x], 1);
        int p1 = atomicAdd(&g_cursor[d.y], 1);
        int p2 = atomicAdd(&g_cursor[d.z], 1);
        int p3 = atomicAdd(&g_cursor[d.w], 1);
        g_adj[p0] = s.x;
        g_adj[p1] = s.y;
        g_adj[p2] = s.z;
        g_adj[p3] = s.w;
    } else {
        for (int k = e; k < E; k++) {
            int pos = atomicAdd(&g_cursor[dst[k]], 1);
            g_adj[pos] = src[k];
        }
    }
}

// ---------------- GEMM1: coalesced smem staging + register tiling ----------
// 256 threads = 256 nodes per block. x staged in 32-col chunks with
// coalesced float4 LDG + 4 scalar STS (stride-33 rows stay conflict-free
// AND avoid the 16B-alignment trap of vector STS on odd rows).
__global__ void __launch_bounds__(256, 3) k_gemm1(const float* __restrict__ x,
                                                  const float* __restrict__ W1) {
    __shared__ float ws[FIN * HID];     // 8 KB
    __shared__ float xs[256][33];       // 33 KB padded
    int tid = threadIdx.x;
    #pragma unroll
    for (int t = 0; t < 8; t++) ws[t * 256 + tid] = W1[t * 256 + tid];
    int node0 = blockIdx.x * 256;
    int node = node0 + tid;
    float acc[16];
    #pragma unroll
    for (int j = 0; j < 16; j++) acc[j] = 0.0f;

    for (int kc = 0; kc < FIN; kc += 32) {
        __syncthreads();
        #pragma unroll
        for (int it = 0; it < 8; it++) {           // 2048 float4, coalesced LDG
            int f = it * 256 + tid;
            int r = f >> 3, c4 = (f & 7) * 4;
            int gi = node0 + r;
            float4 v = (gi < NN)
                ? *(const float4*)&x[(size_t)gi * FIN + kc + c4]
                : make_float4(0.f, 0.f, 0.f, 0.f);
            xs[r][c4 + 0] = v.x;                   // scalar STS, conflict-free
            xs[r][c4 + 1] = v.y;
            xs[r][c4 + 2] = v.z;
            xs[r][c4 + 3] = v.w;
        }
        __syncthreads();
        #pragma unroll 8
        for (int k = 0; k < 32; k++) {
            float xv = xs[tid][k];
            const float4* wr = (const float4*)&ws[(kc + k) * HID];
            float4 w0 = wr[0], w1 = wr[1], w2 = wr[2], w3 = wr[3];
            acc[0]  = fmaf(xv, w0.x, acc[0]);
            acc[1]  = fmaf(xv, w0.y, acc[1]);
            acc[2]  = fmaf(xv, w0.z, acc[2]);
            acc[3]  = fmaf(xv, w0.w, acc[3]);
            acc[4]  = fmaf(xv, w1.x, acc[4]);
            acc[5]  = fmaf(xv, w1.y, acc[5]);
            acc[6]  = fmaf(xv, w1.z, acc[6]);
            acc[7]  = fmaf(xv, w1.w, acc[7]);
            acc[8]  = fmaf(xv, w2.x, acc[8]);
            acc[9]  = fmaf(xv, w2.y, acc[9]);
            acc[10] = fmaf(xv, w2.z, acc[10]);
            acc[11] = fmaf(xv, w2.w, acc[11]);
            acc[12] = fmaf(xv, w3.x, acc[12]);
            acc[13] = fmaf(xv, w3.y, acc[13]);
            acc[14] = fmaf(xv, w3.z, acc[14]);
            acc[15] = fmaf(xv, w3.w, acc[15]);
        }
    }
    if (node >= NN) return;
    float dv = g_dinv[node];
    __half2 h[8];
    #pragma unroll
    for (int j = 0; j < 8; j++)
        h[j] = __floats2half2_rn(acc[2 * j] * dv, acc[2 * j + 1] * dv);
    uint4* o = (uint4*)&g_h1s[node * HID];
    o[0] = *(uint4*)&h[0];
    o[1] = *(uint4*)&h[4];
}

// ---------------- Fused Aggregation1 + ReLU + GEMM2 -------------------------
// 8 lanes per node; lane ln owns feature pair (2ln, 2ln+1) as half2.
__global__ void k_agg1f(const float* __restrict__ b1, const float* __restrict__ W2) {
    int tid = threadIdx.x;
    int node = blockIdx.x * 32 + (tid >> 3);
    int ln = tid & 7;
    if (node >= NN) return;
    const __half2* h1 = (const __half2*)g_h1s;    // [NN*8]
    int beg = g_beg[node];
    int end = beg + g_cnt[node];
    float a0 = 0.0f, a1 = 0.0f;
    int k = beg;
    for (; k + 8 <= end; k += 8) {
        int s0 = g_adj[k],     s1 = g_adj[k + 1], s2 = g_adj[k + 2], s3 = g_adj[k + 3];
        int s4 = g_adj[k + 4], s5 = g_adj[k + 5], s6 = g_adj[k + 6], s7 = g_adj[k + 7];
        float2 v0 = __half22float2(h1[s0 * 8 + ln]);
        float2 v1 = __half22float2(h1[s1 * 8 + ln]);
        float2 v2 = __half22float2(h1[s2 * 8 + ln]);
        float2 v3 = __half22float2(h1[s3 * 8 + ln]);
        float2 v4 = __half22float2(h1[s4 * 8 + ln]);
        float2 v5 = __half22float2(h1[s5 * 8 + ln]);
        float2 v6 = __half22float2(h1[s6 * 8 + ln]);
        float2 v7 = __half22float2(h1[s7 * 8 + ln]);
        a0 += ((v0.x + v1.x) + (v2.x + v3.x)) + ((v4.x + v5.x) + (v6.x + v7.x));
        a1 += ((v0.y + v1.y) + (v2.y + v3.y)) + ((v4.y + v5.y) + (v6.y + v7.y));
    }
    for (; k < end; k++) {
        float2 v = __half22float2(h1[g_adj[k] * 8 + ln]);
        a0 += v.x; a1 += v.y;
    }
    float2 self = __half22float2(h1[node * 8 + ln]);
    float dv = g_dinv[node];
    float o0 = dv * (a0 + self.x);
    float o1 = dv * (a1 + self.y);
    int f0 = ln * 2, f1 = f0 + 1;
    float v0 = fmaxf(o0 + b1[f0], 0.0f);
    float v1 = fmaxf(o1 + b1[f1], 0.0f);
    float c0 = fmaf(v0, W2[f0 * 2 + 0], v1 * W2[f1 * 2 + 0]);
    float c1 = fmaf(v0, W2[f0 * 2 + 1], v1 * W2[f1 * 2 + 1]);
    #pragma unroll
    for (int m = 4; m >= 1; m >>= 1) {
        c0 += __shfl_xor_sync(0xffffffffu, c0, m, 8);
        c1 += __shfl_xor_sync(0xffffffffu, c1, m, 8);
    }
    if (ln == 0) ((float2*)g_h2s)[node] = make_float2(c0 * dv, c1 * dv);
}

// ---------------- Aggregation 2 + bias + log_softmax ------------------------
__global__ void k_agg2g(const float* __restrict__ b2, float* __restrict__ out) {
    int i = blockIdx.x * blockDim.x + threadIdx.x;
    if (i >= NN) return;
    int beg = g_beg[i];
    int end = beg + g_cnt[i];
    float a0 = 0.0f, a1 = 0.0f;
    const float2* h2 = (const float2*)g_h2s;
    int k = beg;
    for (; k + 8 <= end; k += 8) {
        float2 v0 = h2[g_adj[k]];
        float2 v1 = h2[g_adj[k + 1]];
        float2 v2 = h2[g_adj[k + 2]];
        float2 v3 = h2[g_adj[k + 3]];
        float2 v4 = h2[g_adj[k + 4]];
        float2 v5 = h2[g_adj[k + 5]];
        float2 v6 = h2[g_adj[k + 6]];
        float2 v7 = h2[g_adj[k + 7]];
        a0 += ((v0.x + v1.x) + (v2.x + v3.x)) + ((v4.x + v5.x) + (v6.x + v7.x));
        a1 += ((v0.y + v1.y) + (v2.y + v3.y)) + ((v4.y + v5.y) + (v6.y + v7.y));
    }
    for (; k < end; k++) { float2 v = h2[g_adj[k]]; a0 += v.x; a1 += v.y; }
    float dv = g_dinv[i];
    float2 self = h2[i];
    float A = dv * (a0 + self.x) + b2[0];
    float B = dv * (a1 + self.y) + b2[1];
    float m = fmaxf(A, B);
    float lse = m + logf(expf(A - m) + expf(B - m));
    ((float2*)out)[i] = make_float2(A - lse, B - lse);
}

// ---------------- launch ----------------------------------------------------

extern "C" void kernel_launch(void* const* d_in, const int* in_sizes, int n_in,
                              void* d_out, int out_size) {
    const float* x  = (const float*)d_in[0];
    const int*   ei = (const int*)  d_in[1];
    const float* W1 = (const float*)d_in[2];
    const float* b1 = (const float*)d_in[3];
    const float* W2 = (const float*)d_in[4];
    const float* b2 = (const float*)d_in[5];
    float* out = (float*)d_out;

    int E = in_sizes[1] / 2;
    const int* src = ei;
    const int* dst = ei + E;

    void* cnt_ptr = 0;
    cudaGetSymbolAddress(&cnt_ptr, g_cnt);
    cudaMemsetAsync(cnt_ptr, 0, NN * sizeof(int), 0);

    int nt4 = (E + 3) / 4;
    k_count  <<<(nt4 + 255) / 256, 256>>>(dst, E);
    k_offsets<<<NB_OFF, OFF_BLK>>>();
    k_scatter<<<(nt4 + 255) / 256, 256>>>(src, dst, E);
    k_gemm1  <<<(NN + 255) / 256, 256>>>(x, W1);
    k_agg1f  <<<(NN + 31) / 32, 256>>>(b1, W2);
    k_agg2g  <<<(NN + 255) / 256, 256>>>(b2, out);
}

// round 16
// speedup vs baseline: 1.3248x; 1.3248x over previous
#include <cuda_runtime.h>
#include <cuda_fp16.h>
#include <math.h>

#define NN    100000
#define FIN   128
#define HID   16
#define NC    2
#define EMAX  3400000
#define OFF_BLK 1024
#define NB_OFF  ((NN + OFF_BLK - 1) / OFF_BLK)   // 98

// ---------------- scratch (device globals: no allocation allowed) ----------
__device__ int    g_cnt[NN];
__device__ int    g_beg[NN];
__device__ int    g_cursor[NN];
__device__ int    g_total;
__device__ int    g_adj[EMAX];
__device__ float  g_dinv[NN];
__device__ __half g_h1s[NN * HID];   // 32B per node row = 1 L2 sector
__device__ float  g_h2s[NN * NC];

// ---------------- CSR build -------------------------------------------------

__global__ void k_count(const int* __restrict__ dst, int E) {
    int t = blockIdx.x * blockDim.x + threadIdx.x;
    if (t == 0) g_total = 0;                      // consumed only by k_offsets
    int e = t * 4;
    if (e + 3 < E) {
        int4 d = *(const int4*)&dst[e];
        atomicAdd(&g_cnt[d.x], 1);
        atomicAdd(&g_cnt[d.y], 1);
        atomicAdd(&g_cnt[d.z], 1);
        atomicAdd(&g_cnt[d.w], 1);
    } else {
        for (int k = e; k < E; k++) atomicAdd(&g_cnt[dst[k]], 1);
    }
}

// offsets via block scan + single atomic block-base (buckets need only be
// disjoint, not ordered by node id)
__global__ void k_offsets() {
    __shared__ int wsum[32];
    __shared__ int base_sh;
    int tid = threadIdx.x;
    int i = blockIdx.x * OFF_BLK + tid;
    int v = (i < NN) ? g_cnt[i] : 0;
    int lane = tid & 31, wid = tid >> 5;
    int inc = v;
    #pragma unroll
    for (int o = 1; o < 32; o <<= 1) {
        int t = __shfl_up_sync(0xffffffffu, inc, o);
        if (lane >= o) inc += t;
    }
    if (lane == 31) wsum[wid] = inc;
    __syncthreads();
    if (wid == 0) {
        int s = wsum[lane];
        #pragma unroll
        for (int o = 1; o < 32; o <<= 1) {
            int t = __shfl_up_sync(0xffffffffu, s, o);
            if (lane >= o) s += t;
        }
        wsum[lane] = s;
        if (lane == 31) base_sh = atomicAdd(&g_total, s);   // block base
    }
    __syncthreads();
    if (i >= NN) return;
    int wbase = (wid > 0) ? wsum[wid - 1] : 0;
    int beg = base_sh + wbase + inc - v;
    g_beg[i] = beg;
    g_cursor[i] = beg;
    g_dinv[i] = rsqrtf((float)v + 1.0f);          // +1 self loop
}

__global__ void k_scatter(const int* __restrict__ src, const int* __restrict__ dst, int E) {
    int t = blockIdx.x * blockDim.x + threadIdx.x;
    int e = t * 4;
    if (e + 3 < E) {
        int4 s = *(const int4*)&src[e];
        int4 d = *(const int4*)&dst[e];
        int p0 = atomicAdd(&g_cursor[d.x], 1);
        int p1 = atomicAdd(&g_cursor[d.y], 1);
        int p2 = atomicAdd(&g_cursor[d.z], 1);
        int p3 = atomicAdd(&g_cursor[d.w], 1);
        g_adj[p0] = s.x;
        g_adj[p1] = s.y;
        g_adj[p2] = s.z;
        g_adj[p3] = s.w;
    } else {
        for (int k = e; k < E; k++) {
            int pos = atomicAdd(&g_cursor[dst[k]], 1);
            g_adj[pos] = src[k];
        }
    }
}

// ---------------- GEMM1 (measured-best variant, UNSCALED output) ------------
// 128 threads = 128 nodes; each thread owns all 16 outputs in registers.
// Runs on a side stream concurrently with the CSR build (needs only x, W1).
__global__ void k_gemm1(const float* __restrict__ x, const float* __restrict__ W1) {
    __shared__ float xs[128][33];                 // 32-col chunk, padded
    __shared__ float ws[32][16];
    int tid = threadIdx.x;
    int node0 = blockIdx.x * 128;
    int node = node0 + tid;
    float acc[16];
    #pragma unroll
    for (int j = 0; j < 16; j++) acc[j] = 0.0f;

    for (int kc = 0; kc < FIN; kc += 32) {
        __syncthreads();
        for (int it = 0; it < 32; it++) {         // coalesced scalar loads
            int idx = it * 128 + tid;
            int r = idx >> 5, c = idx & 31;
            int gi = node0 + r;
            xs[r][c] = (gi < NN) ? x[(size_t)gi * FIN + kc + c] : 0.0f;
        }
        #pragma unroll
        for (int it = 0; it < 4; it++) {
            int idx = it * 128 + tid;
            ((float*)ws)[idx] = W1[kc * HID + idx];
        }
        __syncthreads();
        #pragma unroll
        for (int k = 0; k < 32; k++) {
            float xv = xs[tid][k];
            const float4* wrow = (const float4*)&ws[k][0];
            float4 w0 = wrow[0], w1 = wrow[1], w2 = wrow[2], w3 = wrow[3];
            acc[0]  = fmaf(xv, w0.x, acc[0]);
            acc[1]  = fmaf(xv, w0.y, acc[1]);
            acc[2]  = fmaf(xv, w0.z, acc[2]);
            acc[3]  = fmaf(xv, w0.w, acc[3]);
            acc[4]  = fmaf(xv, w1.x, acc[4]);
            acc[5]  = fmaf(xv, w1.y, acc[5]);
            acc[6]  = fmaf(xv, w1.z, acc[6]);
            acc[7]  = fmaf(xv, w1.w, acc[7]);
            acc[8]  = fmaf(xv, w2.x, acc[8]);
            acc[9]  = fmaf(xv, w2.y, acc[9]);
            acc[10] = fmaf(xv, w2.z, acc[10]);
            acc[11] = fmaf(xv, w2.w, acc[11]);
            acc[12] = fmaf(xv, w3.x, acc[12]);
            acc[13] = fmaf(xv, w3.y, acc[13]);
            acc[14] = fmaf(xv, w3.z, acc[14]);
            acc[15] = fmaf(xv, w3.w, acc[15]);
        }
    }
    if (node >= NN) return;
    __half2 h[8];
    #pragma unroll
    for (int j = 0; j < 8; j++)
        h[j] = __floats2half2_rn(acc[2 * j], acc[2 * j + 1]);   // unscaled
    uint4* o = (uint4*)&g_h1s[node * HID];
    o[0] = *(uint4*)&h[0];
    o[1] = *(uint4*)&h[4];
}

// ---------------- scale h1 by dinv (join point, tiny) -----------------------
__global__ void k_scale() {
    int i = blockIdx.x * blockDim.x + threadIdx.x;
    if (i >= NN) return;
    float dv = g_dinv[i];
    uint4* p = (uint4*)&g_h1s[i * HID];
    uint4 a = p[0], b = p[1];
    __half2* ha = (__half2*)&a;
    __half2* hb = (__half2*)&b;
    #pragma unroll
    for (int j = 0; j < 4; j++) {
        float2 va = __half22float2(ha[j]);
        float2 vb = __half22float2(hb[j]);
        ha[j] = __floats2half2_rn(va.x * dv, va.y * dv);
        hb[j] = __floats2half2_rn(vb.x * dv, vb.y * dv);
    }
    p[0] = a;
    p[1] = b;
}

// ---------------- Fused Aggregation1 + ReLU + GEMM2 -------------------------
// 8 lanes per node; lane ln owns feature pair (2ln, 2ln+1) as half2.
__global__ void k_agg1f(const float* __restrict__ b1, const float* __restrict__ W2) {
    int tid = threadIdx.x;
    int node = blockIdx.x * 32 + (tid >> 3);
    int ln = tid & 7;
    if (node >= NN) return;
    const __half2* h1 = (const __half2*)g_h1s;    // [NN*8]
    int beg = g_beg[node];
    int end = beg + g_cnt[node];
    float a0 = 0.0f, a1 = 0.0f;
    int k = beg;
    for (; k + 8 <= end; k += 8) {
        int s0 = g_adj[k],     s1 = g_adj[k + 1], s2 = g_adj[k + 2], s3 = g_adj[k + 3];
        int s4 = g_adj[k + 4], s5 = g_adj[k + 5], s6 = g_adj[k + 6], s7 = g_adj[k + 7];
        float2 v0 = __half22float2(h1[s0 * 8 + ln]);
        float2 v1 = __half22float2(h1[s1 * 8 + ln]);
        float2 v2 = __half22float2(h1[s2 * 8 + ln]);
        float2 v3 = __half22float2(h1[s3 * 8 + ln]);
        float2 v4 = __half22float2(h1[s4 * 8 + ln]);
        float2 v5 = __half22float2(h1[s5 * 8 + ln]);
        float2 v6 = __half22float2(h1[s6 * 8 + ln]);
        float2 v7 = __half22float2(h1[s7 * 8 + ln]);
        a0 += ((v0.x + v1.x) + (v2.x + v3.x)) + ((v4.x + v5.x) + (v6.x + v7.x));
        a1 += ((v0.y + v1.y) + (v2.y + v3.y)) + ((v4.y + v5.y) + (v6.y + v7.y));
    }
    for (; k < end; k++) {
        float2 v = __half22float2(h1[g_adj[k] * 8 + ln]);
        a0 += v.x; a1 += v.y;
    }
    float2 self = __half22float2(h1[node * 8 + ln]);
    float dv = g_dinv[node];
    float o0 = dv * (a0 + self.x);
    float o1 = dv * (a1 + self.y);
    int f0 = ln * 2, f1 = f0 + 1;
    float v0 = fmaxf(o0 + b1[f0], 0.0f);
    float v1 = fmaxf(o1 + b1[f1], 0.0f);
    float c0 = fmaf(v0, W2[f0 * 2 + 0], v1 * W2[f1 * 2 + 0]);
    float c1 = fmaf(v0, W2[f0 * 2 + 1], v1 * W2[f1 * 2 + 1]);
    #pragma unroll
    for (int m = 4; m >= 1; m >>= 1) {
        c0 += __shfl_xor_sync(0xffffffffu, c0, m, 8);
        c1 += __shfl_xor_sync(0xffffffffu, c1, m, 8);
    }
    if (ln == 0) ((float2*)g_h2s)[node] = make_float2(c0 * dv, c1 * dv);
}

// ---------------- Aggregation 2 + bias + log_softmax ------------------------
__global__ void k_agg2g(const float* __restrict__ b2, float* __restrict__ out) {
    int i = blockIdx.x * blockDim.x + threadIdx.x;
    if (i >= NN) return;
    int beg = g_beg[i];
    int end = beg + g_cnt[i];
    float a0 = 0.0f, a1 = 0.0f;
    const float2* h2 = (const float2*)g_h2s;
    int k = beg;
    for (; k + 8 <= end; k += 8) {
        float2 v0 = h2[g_adj[k]];
        float2 v1 = h2[g_adj[k + 1]];
        float2 v2 = h2[g_adj[k + 2]];
        float2 v3 = h2[g_adj[k + 3]];
        float2 v4 = h2[g_adj[k + 4]];
        float2 v5 = h2[g_adj[k + 5]];
        float2 v6 = h2[g_adj[k + 6]];
        float2 v7 = h2[g_adj[k + 7]];
        a0 += ((v0.x + v1.x) + (v2.x + v3.x)) + ((v4.x + v5.x) + (v6.x + v7.x));
        a1 += ((v0.y + v1.y) + (v2.y + v3.y)) + ((v4.y + v5.y) + (v6.y + v7.y));
    }
    for (; k < end; k++) { float2 v = h2[g_adj[k]]; a0 += v.x; a1 += v.y; }
    float dv = g_dinv[i];
    float2 self = h2[i];
    float A = dv * (a0 + self.x) + b2[0];
    float B = dv * (a1 + self.y) + b2[1];
    float m = fmaxf(A, B);
    float lse = m + logf(expf(A - m) + expf(B - m));
    ((float2*)out)[i] = make_float2(A - lse, B - lse);
}

// ---------------- launch (two-stream fork/join, graph-capturable) -----------

extern "C" void kernel_launch(void* const* d_in, const int* in_sizes, int n_in,
                              void* d_out, int out_size) {
    const float* x  = (const float*)d_in[0];
    const int*   ei = (const int*)  d_in[1];
    const float* W1 = (const float*)d_in[2];
    const float* b1 = (const float*)d_in[3];
    const float* W2 = (const float*)d_in[4];
    const float* b2 = (const float*)d_in[5];
    float* out = (float*)d_out;

    int E = in_sizes[1] / 2;
    const int* src = ei;
    const int* dst = ei + E;

    // one-time resource setup (no device memory involved; same captured
    // work every call)
    static cudaStream_t s2 = 0;
    static cudaEvent_t evFork = 0, evGemm = 0;
    if (!s2) {
        cudaStreamCreateWithFlags(&s2, cudaStreamNonBlocking);
        cudaEventCreateWithFlags(&evFork, cudaEventDisableTiming);
        cudaEventCreateWithFlags(&evGemm, cudaEventDisableTiming);
    }

    void* cnt_ptr = 0;
    cudaGetSymbolAddress(&cnt_ptr, g_cnt);

    // fork: gemm1 (x,W1 only) runs on s2 concurrently with the CSR build
    cudaEventRecord(evFork, 0);
    cudaStreamWaitEvent(s2, evFork, 0);
    k_gemm1<<<(NN + 127) / 128, 128, 0, s2>>>(x, W1);
    cudaEventRecord(evGemm, s2);

    // main stream: CSR build chain
    cudaMemsetAsync(cnt_ptr, 0, NN * sizeof(int), 0);
    int nt4 = (E + 3) / 4;
    k_count  <<<(nt4 + 255) / 256, 256>>>(dst, E);
    k_offsets<<<NB_OFF, OFF_BLK>>>();
    k_scatter<<<(nt4 + 255) / 256, 256>>>(src, dst, E);

    // join: scale needs both dinv (main) and h1 (s2)
    cudaStreamWaitEvent(0, evGemm, 0);
    k_scale <<<(NN + 255) / 256, 256>>>();
    k_agg1f <<<(NN + 31) / 32, 256>>>(b1, W2);
    k_agg2g <<<(NN + 255) / 256, 256>>>(b2, out);
}